// round 16
// baseline (speedup 1.0000x reference)
#include <cuda_runtime.h>

// JointIntegralRegressor: soft-argmax over [16,24,64,64,64] fp32 heatmaps.
// R16: chunk gradient continued — 128 chunks/slice (49152 CTAs) with
// 64-thread blocks; each thread still does exactly ONE 8-deep front-batched
// load batch (MLP_p1=8; launch_bounds(64,16) preserves the 64-reg budget
// and 32 warps/SM).

#define DIM_W 64
#define DIM_H 64
#define DIM_D 64
#define SLICES 384                           // 16*24
#define SLICE_ELEMS (DIM_D * DIM_H * DIM_W)  // 262144
#define CHUNKS_PER_SLICE 128
#define CHUNK_ELEMS (SLICE_ELEMS / CHUNKS_PER_SLICE)   // 2048
#define NCHUNKS (SLICES * CHUNKS_PER_SLICE)            // 49152
#define P1_THREADS 64
#define V4_PER_THREAD (CHUNK_ELEMS / 4 / P1_THREADS)   // 8
#define BATCH 8

// Scratch for per-chunk partial moments: (s, sx, sy, sz).
__device__ float4 g_partials[NCHUNKS];

__global__ __launch_bounds__(P1_THREADS, 16)   // 64-reg budget, 32 warps/SM
void jir_pass1(const float* __restrict__ in) {
    const int chunk = blockIdx.x;
    const int tid = threadIdx.x;

    const float4* __restrict__ in4 =
        reinterpret_cast<const float4*>(in) + (long long)chunk * (CHUNK_ELEMS / 4);
    const int elem0 = (chunk & (CHUNKS_PER_SLICE - 1)) * CHUNK_ELEMS;

    float s = 0.f, sx = 0.f, sy = 0.f, sz = 0.f;

    // Exactly one front-batched load batch: 8 consecutive LDG.128.
    float4 v[BATCH];
    #pragma unroll
    for (int j = 0; j < BATCH; ++j) {
        v[j] = __ldcs(&in4[j * P1_THREADS + tid]);
    }

    #pragma unroll
    for (int j = 0; j < BATCH; ++j) {
        const int idx4 = j * P1_THREADS + tid;
        const int e  = elem0 + idx4 * 4;
        const float w0 = (float)(e & (DIM_W - 1));
        const int   hd = e >> 6;
        const float hf = (float)(hd & (DIM_H - 1));
        const float df = (float)(hd >> 6);

        const float e0 = __expf(v[j].x);
        const float e1 = __expf(v[j].y);
        const float e2 = __expf(v[j].z);
        const float e3 = __expf(v[j].w);

        const float sp = (e0 + e1) + (e2 + e3);
        // sum_k e_k * (w0 + k) = w0*sp + (e1 + 2*e2 + 3*e3)
        float inner = fmaf(2.f, e2, e1);
        inner       = fmaf(3.f, e3, inner);

        s  += sp;
        sx += fmaf(w0, sp, inner);
        sy  = fmaf(hf, sp, sy);
        sz  = fmaf(df, sp, sz);
    }

    // Block reduction: warp shuffle, then 2 warp-partials via shared memory.
    #pragma unroll
    for (int off = 16; off > 0; off >>= 1) {
        s  += __shfl_down_sync(0xFFFFFFFFu, s,  off);
        sx += __shfl_down_sync(0xFFFFFFFFu, sx, off);
        sy += __shfl_down_sync(0xFFFFFFFFu, sy, off);
        sz += __shfl_down_sync(0xFFFFFFFFu, sz, off);
    }

    __shared__ float4 red[P1_THREADS / 32];
    const int warp = tid >> 5;
    const int lane = tid & 31;
    if (lane == 0) red[warp] = make_float4(s, sx, sy, sz);
    __syncthreads();

    if (tid == 0) {
        float4 acc = red[0];
        acc.x += red[1].x;
        acc.y += red[1].y;
        acc.z += red[1].z;
        acc.w += red[1].w;
        g_partials[chunk] = acc;
    }
}

// One 128-thread block per slice: 128 lanes load one partial each, reduce via
// warp shuffle + shared memory (fixed order -> deterministic).
__global__ __launch_bounds__(128)
void jir_pass2(float* __restrict__ out) {
    const int slice = blockIdx.x;
    const int tid = threadIdx.x;

    const float4 p = g_partials[slice * CHUNKS_PER_SLICE + tid];
    float s = p.x, sx = p.y, sy = p.z, sz = p.w;

    #pragma unroll
    for (int off = 16; off > 0; off >>= 1) {
        s  += __shfl_down_sync(0xFFFFFFFFu, s,  off);
        sx += __shfl_down_sync(0xFFFFFFFFu, sx, off);
        sy += __shfl_down_sync(0xFFFFFFFFu, sy, off);
        sz += __shfl_down_sync(0xFFFFFFFFu, sz, off);
    }

    __shared__ float4 red[4];
    if ((tid & 31) == 0) red[tid >> 5] = make_float4(s, sx, sy, sz);
    __syncthreads();

    if (tid == 0) {
        float fs = 0.f, fsx = 0.f, fsy = 0.f, fsz = 0.f;
        #pragma unroll
        for (int i = 0; i < 4; ++i) {
            fs  += red[i].x;
            fsx += red[i].y;
            fsy += red[i].z;
            fsz += red[i].w;
        }
        const float inv = 1.0f / fs;
        const float scale = 1.0f / 64.0f;
        out[slice * 3 + 0] = fsx * inv * scale - 0.5f;
        out[slice * 3 + 1] = fsy * inv * scale - 0.5f;
        out[slice * 3 + 2] = fsz * inv * scale - 0.5f;
    }
}

extern "C" void kernel_launch(void* const* d_in, const int* in_sizes, int n_in,
                              void* d_out, int out_size) {
    const float* heatmaps = (const float*)d_in[0];
    float* out = (float*)d_out;

    jir_pass1<<<NCHUNKS, P1_THREADS>>>(heatmaps);
    jir_pass2<<<SLICES, 128>>>(out);
}